// round 1
// baseline (speedup 1.0000x reference)
#include <cuda_runtime.h>

// Problem constants
#define BB 16
#define CC 16
#define NN 25
#define HH 16
#define WW 128
#define CH 256              // c*h
#define SS 3200             // n*w
#define BSTRIDE (CC*NN*HH*WW)   // 819200
#define CSTRIDE (NN*HH*WW)      // 51200
#define NSTRIDE (HH*WW)         // 2048

// Scratch (no allocations allowed in kernel_launch)
__device__ float g_p[BB*CH*CH];     // softmax probabilities, 4 MB
__device__ float g_invq[BB*CH];
__device__ float g_invk[BB*CH];

__device__ __forceinline__ int row_base(int b, int t) {
    // t = c*16 + h ; element (n,w) lives at row_base + n*NSTRIDE + w
    return b*BSTRIDE + (t >> 4)*CSTRIDE + (t & 15)*WW;
}

// ---------------------------------------------------------------------------
// Kernel 1: per-row L2 norms of Q and K (rows of length 3200).
// One warp per (b,t) row; 512 CTAs x 256 threads.
// ---------------------------------------------------------------------------
__global__ __launch_bounds__(256) void norms_kernel(const float* __restrict__ q,
                                                    const float* __restrict__ k) {
    int warp = threadIdx.x >> 5, lane = threadIdx.x & 31;
    int row = blockIdx.x * 8 + warp;        // 0..4095
    int b = row >> 8, t = row & 255;
    int base = row_base(b, t) + lane * 4;
    float sq = 0.f, sk = 0.f;
    #pragma unroll
    for (int n = 0; n < NN; ++n) {
        const float4 qa = *(const float4*)(q + base + n*NSTRIDE);
        const float4 ka = *(const float4*)(k + base + n*NSTRIDE);
        sq += qa.x*qa.x + qa.y*qa.y + qa.z*qa.z + qa.w*qa.w;
        sk += ka.x*ka.x + ka.y*ka.y + ka.z*ka.z + ka.w*ka.w;
    }
    #pragma unroll
    for (int o = 16; o; o >>= 1) {
        sq += __shfl_xor_sync(0xffffffffu, sq, o);
        sk += __shfl_xor_sync(0xffffffffu, sk, o);
    }
    if (lane == 0) {
        g_invq[row] = 1.f / fmaxf(sqrtf(sq), 1e-12f);
        g_invk[row] = 1.f / fmaxf(sqrtf(sk), 1e-12f);
    }
}

// ---------------------------------------------------------------------------
// Kernel 2: att = (Qn @ Kn^T), causal mask, softmax -> g_p.
// CTA computes a 32x256 tile of att for one batch. 128 CTAs x 256 threads.
// Thread (tx,ty): rows t0+ty*4+i (i<4), cols tx+32*j (j<8)  -> 32 accumulators.
// s tiled in chunks of 32 through shared memory (pad 36 -> conflict-free).
// ---------------------------------------------------------------------------
#define SC 32
#define KPAD 36
__global__ __launch_bounds__(256) void att_kernel(const float* __restrict__ q,
                                                  const float* __restrict__ k) {
    __shared__ float Qs[32*KPAD];
    __shared__ float Ks[CH*KPAD];

    const int b  = blockIdx.x >> 3;
    const int t0 = (blockIdx.x & 7) * 32;
    const int tid = threadIdx.x;
    const int tx = tid & 31, ty = tid >> 5;

    float acc[4][8];
    #pragma unroll
    for (int i = 0; i < 4; ++i)
        #pragma unroll
        for (int j = 0; j < 8; ++j) acc[i][j] = 0.f;

    // global load indices: thread loads float4 at (row = tid/8, w-offset = (tid%8)*4)
    const int lrow = tid >> 3;
    const int l8   = (tid & 7) * 4;
    const int qbase = row_base(b, t0 + lrow) + l8;
    int kbase[8];
    #pragma unroll
    for (int p = 0; p < 8; ++p) kbase[p] = row_base(b, p*32 + lrow) + l8;

    for (int s0 = 0; s0 < SS; s0 += SC) {
        const int off = (s0 >> 7) * NSTRIDE + (s0 & 127);   // n*2048 + w0
        *(float4*)&Qs[lrow*KPAD + l8] = *(const float4*)(q + qbase + off);
        #pragma unroll
        for (int p = 0; p < 8; ++p)
            *(float4*)&Ks[(p*32 + lrow)*KPAD + l8] = *(const float4*)(k + kbase[p] + off);
        __syncthreads();

        #pragma unroll
        for (int s4 = 0; s4 < SC; s4 += 4) {
            float4 qv[4];
            #pragma unroll
            for (int i = 0; i < 4; ++i)
                qv[i] = *(const float4*)&Qs[(ty*4 + i)*KPAD + s4];
            #pragma unroll
            for (int j = 0; j < 8; ++j) {
                const float4 kv = *(const float4*)&Ks[(tx + 32*j)*KPAD + s4];
                #pragma unroll
                for (int i = 0; i < 4; ++i) {
                    acc[i][j] += qv[i].x*kv.x;
                    acc[i][j] += qv[i].y*kv.y;
                    acc[i][j] += qv[i].z*kv.z;
                    acc[i][j] += qv[i].w*kv.w;
                }
            }
        }
        __syncthreads();
    }

    // scale by inverse norms, causal mask, softmax (row lives in one warp)
    const int bb = b * CH;
    float ik[8];
    #pragma unroll
    for (int j = 0; j < 8; ++j) ik[j] = g_invk[bb + tx + 32*j];

    #pragma unroll
    for (int i = 0; i < 4; ++i) {
        const int trow = t0 + ty*4 + i;
        const float iq = g_invq[bb + trow];
        float vals[8];
        float m = -1e30f;
        #pragma unroll
        for (int j = 0; j < 8; ++j) {
            const int cc = tx + 32*j;
            const float vv = (cc <= trow) ? acc[i][j] * iq * ik[j] : -1e30f;
            vals[j] = vv;
            m = fmaxf(m, vv);
        }
        #pragma unroll
        for (int o = 16; o; o >>= 1) m = fmaxf(m, __shfl_xor_sync(0xffffffffu, m, o));

        float s = 0.f, e[8];
        #pragma unroll
        for (int j = 0; j < 8; ++j) {
            const int cc = tx + 32*j;
            e[j] = (cc <= trow) ? __expf(vals[j] - m) : 0.f;
            s += e[j];
        }
        #pragma unroll
        for (int o = 16; o; o >>= 1) s += __shfl_xor_sync(0xffffffffu, s, o);

        const float inv = 1.f / s;
        float* prow = g_p + (bb + trow)*CH;
        #pragma unroll
        for (int j = 0; j < 8; ++j) prow[tx + 32*j] = e[j] * inv;
    }
}

// ---------------------------------------------------------------------------
// Kernel 3: out = P @ V + token_v.
// CTA computes a 32(t) x 128(w) tile for one (b, t-tile, n). 3200 CTAs.
// Thread (tx,ty): rows t0+ty*4+i, cols w = tx*4 (float4).
// ---------------------------------------------------------------------------
__global__ __launch_bounds__(256) void out_kernel(const float* __restrict__ v,
                                                  float* __restrict__ out) {
    __shared__ float Ps[32*33];
    __shared__ float Vs[32*WW];

    const int n   = blockIdx.x % NN;
    const int tmp = blockIdx.x / NN;
    const int t0  = (tmp & 7) * 32;
    const int b   = tmp >> 3;
    const int tid = threadIdx.x;
    const int tx  = tid & 31, ty = tid >> 5;

    float4 acc[4];
    #pragma unroll
    for (int i = 0; i < 4; ++i) acc[i] = make_float4(0.f, 0.f, 0.f, 0.f);

    const int prow_l = tid >> 5;    // 0..7 (pass stride 8)
    const int pcol_l = tid & 31;

    for (int rc0 = 0; rc0 < CH; rc0 += 32) {
        // P tile: 32(t) x 32(r)
        #pragma unroll
        for (int p = 0; p < 4; ++p) {
            const int r = p*8 + prow_l;
            Ps[r*33 + pcol_l] = g_p[(b*CH + t0 + r)*CH + rc0 + pcol_l];
        }
        // V tile: 32(r) x 128(w)
        #pragma unroll
        for (int p = 0; p < 4; ++p) {
            const int r = p*8 + prow_l;
            const int g = row_base(b, rc0 + r) + n*NSTRIDE + pcol_l*4;
            *(float4*)&Vs[r*WW + pcol_l*4] = *(const float4*)(v + g);
        }
        __syncthreads();

        #pragma unroll
        for (int r = 0; r < 32; ++r) {
            const float4 vv = *(const float4*)&Vs[r*WW + tx*4];
            #pragma unroll
            for (int i = 0; i < 4; ++i) {
                const float pp = Ps[(ty*4 + i)*33 + r];
                acc[i].x += pp * vv.x;
                acc[i].y += pp * vv.y;
                acc[i].z += pp * vv.z;
                acc[i].w += pp * vv.w;
            }
        }
        __syncthreads();
    }

    #pragma unroll
    for (int i = 0; i < 4; ++i) {
        const int t = t0 + ty*4 + i;
        const int a = row_base(b, t) + n*NSTRIDE + tx*4;
        const float4 bu = *(const float4*)(v + a);
        float4 o;
        o.x = acc[i].x + bu.x;
        o.y = acc[i].y + bu.y;
        o.z = acc[i].z + bu.z;
        o.w = acc[i].w + bu.w;
        *(float4*)(out + a) = o;
    }
}

// ---------------------------------------------------------------------------
extern "C" void kernel_launch(void* const* d_in, const int* in_sizes, int n_in,
                              void* d_out, int out_size) {
    const float* q = (const float*)d_in[0];
    const float* k = (const float*)d_in[1];
    const float* v = (const float*)d_in[2];
    float* out = (float*)d_out;

    norms_kernel<<<BB*CH/8, 256>>>(q, k);
    att_kernel<<<BB*8, 256>>>(q, k);
    out_kernel<<<BB*8*NN, 256>>>(v, out);
}